// round 7
// baseline (speedup 1.0000x reference)
#include <cuda_runtime.h>

#define Nn   1000
#define NP   1024      // padded
#define Bb   8

// Scratch (static __device__ — no allocation). Padded to NP.
__device__ float4 g_EA[NP];
__device__ float4 g_EB[NP];       // pad rows = (0,0,0,1) -> d contribution 1, w = 0
__device__ float4 g_xt[2 * NP];   // xt[i] = x[0..7][i] transposed; pad rows = 0
__device__ float  g_cc[32];       // c0/c1/c2 [k][m] (18) + Wf2v (3) + bf2v (1)

// ---- packed f32x2 helpers (Blackwell) ----
__device__ __forceinline__ void ffma2(float2& d, const float2 a, const float2 b) {
    asm("fma.rn.f32x2 %0, %1, %2, %0;"
        : "+l"(reinterpret_cast<unsigned long long&>(d))
        : "l"(reinterpret_cast<const unsigned long long&>(a)),
          "l"(reinterpret_cast<const unsigned long long&>(b)));
}

// ---------------------------------------------------------------------------
// k_pre: 8 blocks x 128, ONE kernel. Each block redundantly computes the
// global sum X from the full contiguous x (2000 float4), so no cross-block
// dependency. Thread g owns row g: transpose, sx, EA/EB.
// ---------------------------------------------------------------------------
__global__ void __launch_bounds__(128) k_pre(
    const float* __restrict__ x,
    const float* __restrict__ W1,   const float* __restrict__ b1,
    const float* __restrict__ W2,   const float* __restrict__ b2,
    const float* __restrict__ Wf1e, const float* __restrict__ bf1e,
    const float* __restrict__ Wf2e, const float* __restrict__ bf2e,
    const float* __restrict__ Wfk,  const float* __restrict__ bfk,
    const float* __restrict__ Wf1v, const float* __restrict__ bf1v,
    const float* __restrict__ Wf2v, const float* __restrict__ bf2v)
{
    __shared__ float s_w[4];
    __shared__ float s_X;
    __shared__ float s_coef[12];   // aA[3], cA[3], aB[3], cB[3]
    const int tid = threadIdx.x;
    const int g   = blockIdx.x * 128 + tid;
    const bool live = (g < Nn);

    // --- my row: transpose + sx ---
    float v[8];
    float sxi = 0.f;
    #pragma unroll
    for (int b = 0; b < 8; b++) {
        v[b] = live ? x[b * Nn + g] : 0.f;
        sxi += v[b];
    }
    g_xt[2 * g]     = make_float4(v[0], v[1], v[2], v[3]);
    g_xt[2 * g + 1] = make_float4(v[4], v[5], v[6], v[7]);

    // --- redundant global X: full x as float4 (8000 floats = 2000 float4) ---
    const float4* x4 = (const float4*)x;
    float xs = 0.f;
    for (int t = tid; t < 2000; t += 128) {
        float4 a = x4[t];
        xs += (a.x + a.y) + (a.z + a.w);
    }
    #pragma unroll
    for (int off = 16; off > 0; off >>= 1)
        xs += __shfl_xor_sync(0xffffffffu, xs, off);
    if ((tid & 31) == 0) s_w[tid >> 5] = xs;
    __syncthreads();
    if (tid == 0) s_X = (s_w[0] + s_w[1]) + (s_w[2] + s_w[3]);
    __syncthreads();
    const float X = s_X;

    // --- coefficients (warp 0 only, redundant across its lanes) ---
    if (tid < 32) {
        float alpha[2], beta[2], gamma[2];
        #pragma unroll
        for (int f = 0; f < 2; f++) {
            float sa = 0.f, sb = 0.f, sg = 0.f;
            #pragma unroll
            for (int e = 0; e < 4; e++) {
                float we = Wf1e[(2 * e) * 2 + f];
                float wo = Wf1e[(2 * e + 1) * 2 + f];
                sa += W1[e] * we;
                sb += W1[e] * wo;
                sg += b1[e] * (we + wo);
            }
            alpha[f] = (float)Nn * sa;
            beta[f]  = sb;
            gamma[f] = (float)Nn * (sg + bf1e[f]);
        }
        float ap[3], cv[3];
        #pragma unroll
        for (int vv = 0; vv < 3; vv++) {
            float a = 0.f, bq = 0.f, gg = 0.f;
            #pragma unroll
            for (int f = 0; f < 2; f++) {
                float w = Wf1v[f * 3 + vv];
                a  += alpha[f] * w;
                bq += beta[f]  * w;
                gg += gamma[f] * w;
            }
            gg += bf1v[vv];
            ap[vv] = a;
            cv[vv] = bq * X + (float)Bb * gg;
        }
        #pragma unroll
        for (int k = 0; k < 3; k++) {
            float s1 = 0.f, s2 = 0.f, s3 = 0.f, s4 = 0.f;
            #pragma unroll
            for (int vv = 0; vv < 3; vv++) {
                float we = Wf2e[(2 * vv) * 3 + k];
                float wo = Wf2e[(2 * vv + 1) * 3 + k];
                s1 += ap[vv] * we;  s2 += cv[vv] * we;
                s3 += ap[vv] * wo;  s4 += cv[vv] * wo;
            }
            if (tid == 0) {
                s_coef[k]     = s1;            // aA
                s_coef[3 + k] = s2 + bf2e[k];  // cA
                s_coef[6 + k] = s3;            // aB
                s_coef[9 + k] = s4;            // cB
            }
        }
        // message-combine constants: block 0, lane 0 only
        if (blockIdx.x == 0 && tid == 0) {
            #pragma unroll
            for (int k = 0; k < 3; k++)
                #pragma unroll
                for (int m = 0; m < 2; m++) {
                    float u1 = 0.f, v1 = 0.f, u2 = 0.f, v2 = 0.f;
                    #pragma unroll
                    for (int e = 0; e < 4; e++) {
                        float we = Wfk[k * 16 + (2 * e) * 2 + m];
                        float wo = Wfk[k * 16 + (2 * e + 1) * 2 + m];
                        u1 += W2[e] * we;  v1 += b2[e] * we;
                        u2 += W2[e] * wo;  v2 += b2[e] * wo;
                    }
                    int km = k * 2 + m;
                    g_cc[km * 3 + 0] = v1 + v2 + bfk[km];
                    g_cc[km * 3 + 1] = u1;
                    g_cc[km * 3 + 2] = u2;
                }
            g_cc[18] = Wf2v[0]; g_cc[19] = Wf2v[1];
            g_cc[20] = Wf2v[2]; g_cc[21] = bf2v[0];
        }
    }
    __syncthreads();

    // --- EA/EB (per-side max-subtracted; exact for factorized softmax) ---
    if (live) {
        float A0 = fmaf(s_coef[0], sxi, s_coef[3]);
        float A1 = fmaf(s_coef[1], sxi, s_coef[4]);
        float A2 = fmaf(s_coef[2], sxi, s_coef[5]);
        float mA = fmaxf(A0, fmaxf(A1, A2));
        g_EA[g] = make_float4(__expf(A0 - mA), __expf(A1 - mA), __expf(A2 - mA), 0.f);
        float B0 = fmaf(s_coef[6], sxi, s_coef[9]);
        float B1 = fmaf(s_coef[7], sxi, s_coef[10]);
        float B2 = fmaf(s_coef[8], sxi, s_coef[11]);
        float mB = fmaxf(B0, fmaxf(B1, B2));
        g_EB[g] = make_float4(__expf(B0 - mB), __expf(B1 - mB), __expf(B2 - mB), 0.f);
    } else {
        g_EA[g] = make_float4(0.f, 0.f, 0.f, 0.f);
        g_EB[g] = make_float4(0.f, 0.f, 0.f, 1.f);  // pad: d += 1, w = 0
    }
}

// ---------------------------------------------------------------------------
// k_main: TWO rows per block (grid 500 x 128). The eb/x loads are shared by
// both rows; Montgomery batch inversion over all 8 denominators (1 MUFU per
// 8 pairs). 19 accumulators per row. Two 32-slot exchange reductions.
// ---------------------------------------------------------------------------
__global__ void __launch_bounds__(128, 4) k_main(float* __restrict__ out)
{
    const int i0   = blockIdx.x * 2;
    const int i1   = i0 + 1;
    const int tid  = threadIdx.x;
    const int lane = tid & 31;
    const int warp = tid >> 5;
    const float4 eaA = g_EA[i0];
    const float4 eaB = g_EA[i1];

    // folded coefficients q[m][k] = c2[k,m] * ea_k, per row
    float qA0[3], qA1[3], qB0[3], qB1[3];
    {
        const float evA[3] = {eaA.x, eaA.y, eaA.z};
        const float evB[3] = {eaB.x, eaB.y, eaB.z};
        #pragma unroll
        for (int k = 0; k < 3; k++) {
            float c20 = g_cc[(k * 2 + 0) * 3 + 2];
            float c21 = g_cc[(k * 2 + 1) * 3 + 2];
            qA0[k] = c20 * evA[k];  qA1[k] = c21 * evA[k];
            qB0[k] = c20 * evB[k];  qB1[k] = c21 * evB[k];
        }
    }

    float tA0 = 0.f, tA1 = 0.f, tA2 = 0.f;
    float tB0 = 0.f, tB1 = 0.f, tB2 = 0.f;
    float2 vA0[4], vA1[4], vB0[4], vB1[4];
    #pragma unroll
    for (int bp = 0; bp < 4; bp++) {
        vA0[bp] = make_float2(0.f, 0.f); vA1[bp] = make_float2(0.f, 0.f);
        vB0[bp] = make_float2(0.f, 0.f); vB1[bp] = make_float2(0.f, 0.f);
    }

    #pragma unroll 1
    for (int half = 0; half < 2; half++) {
        float4 eb[4], xa[4], xb[4];
        #pragma unroll
        for (int t = 0; t < 4; t++) {
            const int j = (half * 4 + t) * 128 + tid;
            eb[t] = g_EB[j];
            xa[t] = g_xt[2 * j];
            xb[t] = g_xt[2 * j + 1];
        }
        float dA[4], dB[4];
        #pragma unroll
        for (int t = 0; t < 4; t++) {
            dA[t] = fmaf(eaA.x, eb[t].x, fmaf(eaA.y, eb[t].y, fmaf(eaA.z, eb[t].z, eb[t].w)));
            dB[t] = fmaf(eaB.x, eb[t].x, fmaf(eaB.y, eb[t].y, fmaf(eaB.z, eb[t].z, eb[t].w)));
        }
        // Montgomery over 8 denominators: 1 reciprocal per 8 pairs.
        // d in (1,4] -> product <= 65536: no range risk.
        float p0 = dA[0];
        float p1 = p0 * dA[1];
        float p2 = p1 * dA[2];
        float p3 = p2 * dA[3];
        float p4 = p3 * dB[0];
        float p5 = p4 * dB[1];
        float p6 = p5 * dB[2];
        float p7 = p6 * dB[3];
        float r  = __fdividef(1.f, p7);
        float iB3 = r * p6;  r *= dB[3];
        float iB2 = r * p5;  r *= dB[2];
        float iB1 = r * p4;  r *= dB[1];
        float iB0 = r * p3;  r *= dB[0];
        float iA3 = r * p2;  r *= dA[3];
        float iA2 = r * p1;  r *= dA[2];
        float iA1 = r * p0;  r *= dA[1];
        float iA0 = r;
        float invA[4] = {iA0, iA1, iA2, iA3};
        float invB[4] = {iB0, iB1, iB2, iB3};

        #pragma unroll
        for (int t = 0; t < 4; t++) {
            float2 xp[4] = { make_float2(xa[t].x, xa[t].y), make_float2(xa[t].z, xa[t].w),
                             make_float2(xb[t].x, xb[t].y), make_float2(xb[t].z, xb[t].w) };
            // row A
            {
                float w0 = eb[t].x * invA[t];
                float w1 = eb[t].y * invA[t];
                float w2 = eb[t].z * invA[t];
                tA0 += w0; tA1 += w1; tA2 += w2;
                float s0 = fmaf(qA0[0], w0, fmaf(qA0[1], w1, qA0[2] * w2));
                float s1 = fmaf(qA1[0], w0, fmaf(qA1[1], w1, qA1[2] * w2));
                float2 sp0 = make_float2(s0, s0);
                float2 sp1 = make_float2(s1, s1);
                #pragma unroll
                for (int bp = 0; bp < 4; bp++) {
                    ffma2(vA0[bp], sp0, xp[bp]);
                    ffma2(vA1[bp], sp1, xp[bp]);
                }
            }
            // row B
            {
                float w0 = eb[t].x * invB[t];
                float w1 = eb[t].y * invB[t];
                float w2 = eb[t].z * invB[t];
                tB0 += w0; tB1 += w1; tB2 += w2;
                float s0 = fmaf(qB0[0], w0, fmaf(qB0[1], w1, qB0[2] * w2));
                float s1 = fmaf(qB1[0], w0, fmaf(qB1[1], w1, qB1[2] * w2));
                float2 sp0 = make_float2(s0, s0);
                float2 sp1 = make_float2(s1, s1);
                #pragma unroll
                for (int bp = 0; bp < 4; bp++) {
                    ffma2(vB0[bp], sp0, xp[bp]);
                    ffma2(vB1[bp], sp1, xp[bp]);
                }
            }
        }
    }

    // two 32-slot distributed exchanges (rows interleaved for ILP)
    float vv[2][32];
    vv[0][0] = tA0; vv[0][1] = tA1; vv[0][2] = tA2;
    vv[1][0] = tB0; vv[1][1] = tB1; vv[1][2] = tB2;
    #pragma unroll
    for (int bp = 0; bp < 4; bp++) {
        vv[0][3 + 2 * bp]      = vA0[bp].x;  vv[0][3 + 2 * bp + 1]  = vA0[bp].y;
        vv[0][11 + 2 * bp]     = vA1[bp].x;  vv[0][11 + 2 * bp + 1] = vA1[bp].y;
        vv[1][3 + 2 * bp]      = vB0[bp].x;  vv[1][3 + 2 * bp + 1]  = vB0[bp].y;
        vv[1][11 + 2 * bp]     = vB1[bp].x;  vv[1][11 + 2 * bp + 1] = vB1[bp].y;
    }
    #pragma unroll
    for (int s = 19; s < 32; s++) { vv[0][s] = 0.f; vv[1][s] = 0.f; }

    #pragma unroll
    for (int lev = 0; lev < 5; lev++) {
        const int d = 1 << lev;
        const int half = 16 >> lev;
        const bool up = (lane & d) != 0;
        #pragma unroll
        for (int row = 0; row < 2; row++)
            #pragma unroll
            for (int s = 0; s < half; s++) {
                float keep = up ? vv[row][s + half] : vv[row][s];
                float send = up ? vv[row][s] : vv[row][s + half];
                float recv = __shfl_xor_sync(0xffffffffu, send, d);
                vv[row][s] = keep + recv;
            }
    }
    const int br = ((lane & 1) << 4) | ((lane & 2) << 2) | (lane & 4)
                 | ((lane & 8) >> 2) | ((lane & 16) >> 4);

    __shared__ float s_v[4][64];
    s_v[warp][br]      = vv[0][0];
    s_v[warp][32 + br] = vv[1][0];
    __syncthreads();

    if (tid < 16) {
        const int b   = tid & 7;
        const int row = tid >> 3;             // 0 -> i0, 1 -> i1
        const int i   = row ? i1 : i0;
        const int base = row * 32;
        const float4 ea = row ? eaB : eaA;
        const float eav[3] = {ea.x, ea.y, ea.z};
        float xbi = ((const float*)&g_xt[2 * i])[b];
        float T0 = (s_v[0][base + 0] + s_v[1][base + 0]) + (s_v[2][base + 0] + s_v[3][base + 0]);
        float T1 = (s_v[0][base + 1] + s_v[1][base + 1]) + (s_v[2][base + 1] + s_v[3][base + 1]);
        float T2 = (s_v[0][base + 2] + s_v[1][base + 2]) + (s_v[2][base + 2] + s_v[3][base + 2]);
        float V0 = (s_v[0][base + 3 + b] + s_v[1][base + 3 + b])
                 + (s_v[2][base + 3 + b] + s_v[3][base + 3 + b]);
        float V1 = (s_v[0][base + 11 + b] + s_v[1][base + 11 + b])
                 + (s_v[2][base + 11 + b] + s_v[3][base + 11 + b]);
        float eaT[3] = {eav[0] * T0, eav[1] * T1, eav[2] * T2};
        float ve0 = V0, ve1 = V1;
        #pragma unroll
        for (int k = 0; k < 3; k++) {
            ve0 += fmaf(xbi, g_cc[(k * 2 + 0) * 3 + 1], g_cc[(k * 2 + 0) * 3 + 0]) * eaT[k];
            ve1 += fmaf(xbi, g_cc[(k * 2 + 1) * 3 + 1], g_cc[(k * 2 + 1) * 3 + 0]) * eaT[k];
        }
        out[b * Nn + i] = xbi * (1.f + g_cc[20]) + g_cc[21]
                        + ve0 * g_cc[18] + ve1 * g_cc[19];
    }
}

extern "C" void kernel_launch(void* const* d_in, const int* in_sizes, int n_in,
                              void* d_out, int out_size)
{
    (void)in_sizes; (void)n_in; (void)out_size;
    k_pre<<<8, 128>>>(
        (const float*)d_in[0],
        (const float*)d_in[1],  (const float*)d_in[2],
        (const float*)d_in[3],  (const float*)d_in[4],
        (const float*)d_in[5],  (const float*)d_in[6],
        (const float*)d_in[7],  (const float*)d_in[8],
        (const float*)d_in[9],  (const float*)d_in[10],
        (const float*)d_in[11], (const float*)d_in[12],
        (const float*)d_in[13], (const float*)d_in[14]);
    k_main<<<500, 128>>>((float*)d_out);
}

// round 8
// speedup vs baseline: 1.0195x; 1.0195x over previous
#include <cuda_runtime.h>

#define Nn      1000
#define NP      1024
#define Bb      8
#define GRID    125
#define NTHREAD 256

// Scratch (static __device__ — no allocation). Padded to NP.
__device__ float4 g_EA[NP];
__device__ float4 g_EB[NP];       // pad rows = (0,0,0,1) -> d contribution 1, w = 0
__device__ float4 g_xt[2 * NP];   // xt[i] = x[0..7][i] transposed; pad rows = 0
__device__ float  g_cc[32];       // c0/c1/c2 [k][m] (18) + Wf2v (3) + bf2v (1)
__device__ unsigned long long g_bar = 0ULL;   // monotonic ticket counter (never reset)

// ---- packed f32x2 helper (Blackwell) ----
__device__ __forceinline__ void ffma2(float2& d, const float2 a, const float2 b) {
    asm("fma.rn.f32x2 %0, %1, %2, %0;"
        : "+l"(reinterpret_cast<unsigned long long&>(d))
        : "l"(reinterpret_cast<const unsigned long long&>(a)),
          "l"(reinterpret_cast<const unsigned long long&>(b)));
}

__device__ __forceinline__ int brev5(int s) {
    return ((s & 1) << 4) | ((s & 2) << 2) | (s & 4) | ((s & 8) >> 2) | ((s & 16) >> 4);
}

// ---------------------------------------------------------------------------
// Single fused kernel. 125 blocks x 256 threads, all co-resident (<=148 SMs).
// Phase 1 (blocks 0..3): transpose x, compute X redundantly, coefficients,
// EA/EB. Grid-wide ticket barrier. Phase 2: one warp per row i, warp-local
// reduction, shfl-gather epilogue. No smem in phase 2.
// ---------------------------------------------------------------------------
__global__ void __launch_bounds__(NTHREAD, 1) k_all(
    const float* __restrict__ x,
    const float* __restrict__ W1,   const float* __restrict__ b1,
    const float* __restrict__ W2,   const float* __restrict__ b2,
    const float* __restrict__ Wf1e, const float* __restrict__ bf1e,
    const float* __restrict__ Wf2e, const float* __restrict__ bf2e,
    const float* __restrict__ Wfk,  const float* __restrict__ bfk,
    const float* __restrict__ Wf1v, const float* __restrict__ bf1v,
    const float* __restrict__ Wf2v, const float* __restrict__ bf2v,
    float* __restrict__ out)
{
    const int tid = threadIdx.x;
    const int bid = blockIdx.x;

    // ================= Phase 1: blocks 0..3 cover rows 0..1023 =============
    if (bid < 4) {
        __shared__ float s_w[8];
        __shared__ float s_X;
        __shared__ float s_coef[12];   // aA[3], cA[3], aB[3], cB[3]

        const int g = bid * NTHREAD + tid;   // 0..1023
        const bool live = (g < Nn);

        float vr[8];
        float sxi = 0.f;
        #pragma unroll
        for (int b = 0; b < 8; b++) {
            vr[b] = live ? x[b * Nn + g] : 0.f;
            sxi += vr[b];
        }
        g_xt[2 * g]     = make_float4(vr[0], vr[1], vr[2], vr[3]);
        g_xt[2 * g + 1] = make_float4(vr[4], vr[5], vr[6], vr[7]);

        // redundant global X: full contiguous x as 2000 float4 per block
        const float4* x4 = (const float4*)x;
        float xs = 0.f;
        for (int t = tid; t < 2000; t += NTHREAD) {
            float4 a = x4[t];
            xs += (a.x + a.y) + (a.z + a.w);
        }
        #pragma unroll
        for (int off = 16; off > 0; off >>= 1)
            xs += __shfl_xor_sync(0xffffffffu, xs, off);
        if ((tid & 31) == 0) s_w[tid >> 5] = xs;
        __syncthreads();
        if (tid == 0) {
            float s = 0.f;
            #pragma unroll
            for (int w = 0; w < 8; w++) s += s_w[w];   // fixed order
            s_X = s;
        }
        __syncthreads();
        const float X = s_X;

        // coefficients (warp 0, redundant across lanes)
        if (tid < 32) {
            float alpha[2], beta[2], gamma[2];
            #pragma unroll
            for (int f = 0; f < 2; f++) {
                float sa = 0.f, sb = 0.f, sg = 0.f;
                #pragma unroll
                for (int e = 0; e < 4; e++) {
                    float we = Wf1e[(2 * e) * 2 + f];
                    float wo = Wf1e[(2 * e + 1) * 2 + f];
                    sa += W1[e] * we;
                    sb += W1[e] * wo;
                    sg += b1[e] * (we + wo);
                }
                alpha[f] = (float)Nn * sa;
                beta[f]  = sb;
                gamma[f] = (float)Nn * (sg + bf1e[f]);
            }
            float ap[3], cv[3];
            #pragma unroll
            for (int vv = 0; vv < 3; vv++) {
                float a = 0.f, bq = 0.f, gg = 0.f;
                #pragma unroll
                for (int f = 0; f < 2; f++) {
                    float w = Wf1v[f * 3 + vv];
                    a  += alpha[f] * w;
                    bq += beta[f]  * w;
                    gg += gamma[f] * w;
                }
                gg += bf1v[vv];
                ap[vv] = a;
                cv[vv] = bq * X + (float)Bb * gg;
            }
            #pragma unroll
            for (int k = 0; k < 3; k++) {
                float s1 = 0.f, s2 = 0.f, s3 = 0.f, s4 = 0.f;
                #pragma unroll
                for (int vv = 0; vv < 3; vv++) {
                    float we = Wf2e[(2 * vv) * 3 + k];
                    float wo = Wf2e[(2 * vv + 1) * 3 + k];
                    s1 += ap[vv] * we;  s2 += cv[vv] * we;
                    s3 += ap[vv] * wo;  s4 += cv[vv] * wo;
                }
                if (tid == 0) {
                    s_coef[k]     = s1;            // aA
                    s_coef[3 + k] = s2 + bf2e[k];  // cA
                    s_coef[6 + k] = s3;            // aB
                    s_coef[9 + k] = s4;            // cB
                }
            }
            // message-combine constants: block 0, lane 0 only
            if (bid == 0 && tid == 0) {
                #pragma unroll
                for (int k = 0; k < 3; k++)
                    #pragma unroll
                    for (int m = 0; m < 2; m++) {
                        float u1 = 0.f, v1 = 0.f, u2 = 0.f, v2 = 0.f;
                        #pragma unroll
                        for (int e = 0; e < 4; e++) {
                            float we = Wfk[k * 16 + (2 * e) * 2 + m];
                            float wo = Wfk[k * 16 + (2 * e + 1) * 2 + m];
                            u1 += W2[e] * we;  v1 += b2[e] * we;
                            u2 += W2[e] * wo;  v2 += b2[e] * wo;
                        }
                        int km = k * 2 + m;
                        g_cc[km * 3 + 0] = v1 + v2 + bfk[km];
                        g_cc[km * 3 + 1] = u1;
                        g_cc[km * 3 + 2] = u2;
                    }
                g_cc[18] = Wf2v[0]; g_cc[19] = Wf2v[1];
                g_cc[20] = Wf2v[2]; g_cc[21] = bf2v[0];
            }
        }
        __syncthreads();

        // EA/EB (per-side max-subtracted; exact for factorized softmax)
        if (live) {
            float A0 = fmaf(s_coef[0], sxi, s_coef[3]);
            float A1 = fmaf(s_coef[1], sxi, s_coef[4]);
            float A2 = fmaf(s_coef[2], sxi, s_coef[5]);
            float mA = fmaxf(A0, fmaxf(A1, A2));
            g_EA[g] = make_float4(__expf(A0 - mA), __expf(A1 - mA), __expf(A2 - mA), 0.f);
            float B0 = fmaf(s_coef[6], sxi, s_coef[9]);
            float B1 = fmaf(s_coef[7], sxi, s_coef[10]);
            float B2 = fmaf(s_coef[8], sxi, s_coef[11]);
            float mB = fmaxf(B0, fmaxf(B1, B2));
            g_EB[g] = make_float4(__expf(B0 - mB), __expf(B1 - mB), __expf(B2 - mB), 0.f);
        } else {
            g_EA[g] = make_float4(0.f, 0.f, 0.f, 0.f);
            g_EB[g] = make_float4(0.f, 0.f, 0.f, 1.f);  // pad: d += 1, w = 0
        }
    }

    // ================= grid-wide ticket barrier (replay-safe) ===============
    __syncthreads();
    __threadfence();                       // release phase-1 writes
    if (tid == 0) {
        unsigned long long ticket = atomicAdd(&g_bar, 1ULL);
        unsigned long long target = ticket - (ticket % GRID) + GRID;
        while (*(volatile unsigned long long*)&g_bar < target) { }
    }
    __syncthreads();
    __threadfence();                       // acquire

    // ================= Phase 2: one warp per row ============================
    const int lane = tid & 31;
    const int warp = tid >> 5;
    const int i    = bid * 8 + warp;       // 0..999 exactly
    const float4 ea = g_EA[i];
    const float eav[3] = {ea.x, ea.y, ea.z};

    // folded coefficients q[m][k] = c2[k,m] * ea_k
    float q0[3], q1[3];
    #pragma unroll
    for (int k = 0; k < 3; k++) {
        q0[k] = g_cc[(k * 2 + 0) * 3 + 2] * eav[k];
        q1[k] = g_cc[(k * 2 + 1) * 3 + 2] * eav[k];
    }

    float t0 = 0.f, t1 = 0.f, t2 = 0.f;
    float2 a0[4], a1[4];                   // V0/V1 pairs (b=2bp, 2bp+1)
    #pragma unroll
    for (int bp = 0; bp < 4; bp++) {
        a0[bp] = make_float2(0.f, 0.f);
        a1[bp] = make_float2(0.f, 0.f);
    }

    #pragma unroll 1
    for (int u = 0; u < 8; u++) {
        float4 eb[4], xa[4], xb[4];
        #pragma unroll
        for (int t = 0; t < 4; t++) {
            const int j = (u * 4 + t) * 32 + lane;
            eb[t] = g_EB[j];
            xa[t] = g_xt[2 * j];
            xb[t] = g_xt[2 * j + 1];
        }
        float d[4];
        #pragma unroll
        for (int t = 0; t < 4; t++)
            d[t] = fmaf(ea.x, eb[t].x, fmaf(ea.y, eb[t].y, fmaf(ea.z, eb[t].z, eb[t].w)));
        // Montgomery batch inversion: 1 MUFU per 4 pairs; d in (1,4] -> safe
        float p1 = d[0] * d[1];
        float p2 = p1 * d[2];
        float p3 = p2 * d[3];
        float r  = __fdividef(1.f, p3);
        float inv[4];
        inv[3]   = r * p2;
        float r2 = r * d[3];
        inv[2]   = r2 * p1;
        float r1 = r2 * d[2];
        inv[1]   = r1 * d[0];
        inv[0]   = r1 * d[1];

        #pragma unroll
        for (int t = 0; t < 4; t++) {
            float w0 = eb[t].x * inv[t];
            float w1 = eb[t].y * inv[t];
            float w2 = eb[t].z * inv[t];
            t0 += w0; t1 += w1; t2 += w2;
            float s0 = fmaf(q0[0], w0, fmaf(q0[1], w1, q0[2] * w2));
            float s1 = fmaf(q1[0], w0, fmaf(q1[1], w1, q1[2] * w2));
            float2 xp[4] = { make_float2(xa[t].x, xa[t].y), make_float2(xa[t].z, xa[t].w),
                             make_float2(xb[t].x, xb[t].y), make_float2(xb[t].z, xb[t].w) };
            float2 sp0 = make_float2(s0, s0);
            float2 sp1 = make_float2(s1, s1);
            #pragma unroll
            for (int bp = 0; bp < 4; bp++) {
                ffma2(a0[bp], sp0, xp[bp]);
                ffma2(a1[bp], sp1, xp[bp]);
            }
        }
    }

    // 19 values -> 32 slots; distributed exchange reduce (lane l ends with
    // total of slot bitrev5(l) in vv[0])
    float vv[32];
    vv[0] = t0; vv[1] = t1; vv[2] = t2;
    #pragma unroll
    for (int bp = 0; bp < 4; bp++) {
        vv[3 + 2 * bp]      = a0[bp].x;  vv[3 + 2 * bp + 1]  = a0[bp].y;
        vv[11 + 2 * bp]     = a1[bp].x;  vv[11 + 2 * bp + 1] = a1[bp].y;
    }
    #pragma unroll
    for (int s = 19; s < 32; s++) vv[s] = 0.f;

    #pragma unroll
    for (int lev = 0; lev < 5; lev++) {
        const int dd = 1 << lev;
        const int half = 16 >> lev;
        const bool up = (lane & dd) != 0;
        #pragma unroll
        for (int s = 0; s < half; s++) {
            float keep = up ? vv[s + half] : vv[s];
            float send = up ? vv[s] : vv[s + half];
            float recv = __shfl_xor_sync(0xffffffffu, send, dd);
            vv[s] = keep + recv;
        }
    }

    // gather the needed slots via shfl (all lanes participate)
    const int b  = lane & 7;
    float T0 = __shfl_sync(0xffffffffu, vv[0], 0);               // slot 0
    float T1 = __shfl_sync(0xffffffffu, vv[0], 16);              // slot 1
    float T2 = __shfl_sync(0xffffffffu, vv[0], 8);               // slot 2
    float V0 = __shfl_sync(0xffffffffu, vv[0], brev5(3 + b));    // slot 3+b
    float V1 = __shfl_sync(0xffffffffu, vv[0], brev5(11 + b));   // slot 11+b

    if (lane < 8) {
        float xbi = ((const float*)&g_xt[2 * i])[b];
        float eaT[3] = {eav[0] * T0, eav[1] * T1, eav[2] * T2};
        float ve0 = V0, ve1 = V1;
        #pragma unroll
        for (int k = 0; k < 3; k++) {
            ve0 += fmaf(xbi, g_cc[(k * 2 + 0) * 3 + 1], g_cc[(k * 2 + 0) * 3 + 0]) * eaT[k];
            ve1 += fmaf(xbi, g_cc[(k * 2 + 1) * 3 + 1], g_cc[(k * 2 + 1) * 3 + 0]) * eaT[k];
        }
        out[b * Nn + i] = xbi * (1.f + g_cc[20]) + g_cc[21]
                        + ve0 * g_cc[18] + ve1 * g_cc[19];
    }
}

extern "C" void kernel_launch(void* const* d_in, const int* in_sizes, int n_in,
                              void* d_out, int out_size)
{
    (void)in_sizes; (void)n_in; (void)out_size;
    k_all<<<GRID, NTHREAD>>>(
        (const float*)d_in[0],
        (const float*)d_in[1],  (const float*)d_in[2],
        (const float*)d_in[3],  (const float*)d_in[4],
        (const float*)d_in[5],  (const float*)d_in[6],
        (const float*)d_in[7],  (const float*)d_in[8],
        (const float*)d_in[9],  (const float*)d_in[10],
        (const float*)d_in[11], (const float*)d_in[12],
        (const float*)d_in[13], (const float*)d_in[14],
        (float*)d_out);
}

// round 9
// speedup vs baseline: 1.1805x; 1.1579x over previous
#include <cuda_runtime.h>

#define Nn      1000
#define NP      1024
#define Bb      8
#define GRID    125
#define NTHREAD 512

// Scratch (static __device__ — no allocation). Padded to NP.
__device__ float4 g_EA[NP];
__device__ float4 g_EB[NP];       // pad rows = (0,0,0,1) -> d contribution 1, w = 0
__device__ float4 g_xt[2 * NP];   // xt[i] = x[0..7][i] transposed; pad rows = 0
__device__ float  g_cc[32];       // c0/c1/c2 [k][m] (18) + Wf2v (3) + bf2v (1)
__device__ unsigned long long g_bar = 0ULL;   // monotonic ticket counter (never reset)

// ---- packed f32x2 helper (Blackwell) ----
__device__ __forceinline__ void ffma2(float2& d, const float2 a, const float2 b) {
    asm("fma.rn.f32x2 %0, %1, %2, %0;"
        : "+l"(reinterpret_cast<unsigned long long&>(d))
        : "l"(reinterpret_cast<const unsigned long long&>(a)),
          "l"(reinterpret_cast<const unsigned long long&>(b)));
}

// ---------------------------------------------------------------------------
// Single persistent kernel: 125 blocks x 512 threads (1 block/SM, all
// co-resident). Phase 1: each block preps ITS OWN 8 rows + redundant global
// X + coefficients. Grid ticket barrier. Phase 2: 2 warps per row (16 j's
// per lane), warp exchange-reduce, smem pair-combine, direct output.
// ---------------------------------------------------------------------------
__global__ void __launch_bounds__(NTHREAD, 1) k_all(
    const float* __restrict__ x,
    const float* __restrict__ W1,   const float* __restrict__ b1,
    const float* __restrict__ W2,   const float* __restrict__ b2,
    const float* __restrict__ Wf1e, const float* __restrict__ bf1e,
    const float* __restrict__ Wf2e, const float* __restrict__ bf2e,
    const float* __restrict__ Wfk,  const float* __restrict__ bfk,
    const float* __restrict__ Wf1v, const float* __restrict__ bf1v,
    const float* __restrict__ Wf2v, const float* __restrict__ bf2v,
    float* __restrict__ out)
{
    __shared__ float s_w[16];
    __shared__ float s_X;
    __shared__ float s_coef[12];     // aA[3], cA[3], aB[3], cB[3]
    __shared__ float s_v[16][32];    // per-warp reduced slots

    const int tid = threadIdx.x;
    const int bid = blockIdx.x;

    // ===================== Phase 1 (all blocks work) ========================
    // threads 0..7: this block's 8 rows (same rows consumed in phase 2)
    const int myrow = bid * 8 + tid;          // valid for tid < 8 (max 999)
    float sxi = 0.f;
    if (tid < 8) {
        float vr[8];
        #pragma unroll
        for (int b = 0; b < 8; b++) {
            vr[b] = x[b * Nn + myrow];
            sxi += vr[b];
        }
        g_xt[2 * myrow]     = make_float4(vr[0], vr[1], vr[2], vr[3]);
        g_xt[2 * myrow + 1] = make_float4(vr[4], vr[5], vr[6], vr[7]);
    } else if (bid == GRID - 1 && tid < 32) {
        // pad rows 1000..1023 (24 rows), written by block 124 threads 8..31
        const int p = Nn + (tid - 8);
        g_xt[2 * p]     = make_float4(0.f, 0.f, 0.f, 0.f);
        g_xt[2 * p + 1] = make_float4(0.f, 0.f, 0.f, 0.f);
        g_EA[p] = make_float4(0.f, 0.f, 0.f, 0.f);
        g_EB[p] = make_float4(0.f, 0.f, 0.f, 1.f);   // d += 1, w = 0
    }

    // redundant global X: contiguous x as 2000 float4 (L2-shared across blocks)
    {
        const float4* x4 = (const float4*)x;
        float xs = 0.f;
        #pragma unroll 1
        for (int t = tid; t < 2000; t += NTHREAD) {
            float4 a = x4[t];
            xs += (a.x + a.y) + (a.z + a.w);
        }
        #pragma unroll
        for (int off = 16; off > 0; off >>= 1)
            xs += __shfl_xor_sync(0xffffffffu, xs, off);
        if ((tid & 31) == 0) s_w[tid >> 5] = xs;
    }
    __syncthreads();
    if (tid == 0) {
        float s = 0.f;
        #pragma unroll
        for (int w = 0; w < 16; w++) s += s_w[w];    // fixed order
        s_X = s;
    }
    __syncthreads();
    const float X = s_X;

    // coefficients (warp 0, redundant across lanes)
    if (tid < 32) {
        float alpha[2], beta[2], gamma[2];
        #pragma unroll
        for (int f = 0; f < 2; f++) {
            float sa = 0.f, sb = 0.f, sg = 0.f;
            #pragma unroll
            for (int e = 0; e < 4; e++) {
                float we = Wf1e[(2 * e) * 2 + f];
                float wo = Wf1e[(2 * e + 1) * 2 + f];
                sa += W1[e] * we;
                sb += W1[e] * wo;
                sg += b1[e] * (we + wo);
            }
            alpha[f] = (float)Nn * sa;
            beta[f]  = sb;
            gamma[f] = (float)Nn * (sg + bf1e[f]);
        }
        float ap[3], cv[3];
        #pragma unroll
        for (int vv = 0; vv < 3; vv++) {
            float a = 0.f, bq = 0.f, gg = 0.f;
            #pragma unroll
            for (int f = 0; f < 2; f++) {
                float w = Wf1v[f * 3 + vv];
                a  += alpha[f] * w;
                bq += beta[f]  * w;
                gg += gamma[f] * w;
            }
            gg += bf1v[vv];
            ap[vv] = a;
            cv[vv] = bq * X + (float)Bb * gg;
        }
        #pragma unroll
        for (int k = 0; k < 3; k++) {
            float s1 = 0.f, s2 = 0.f, s3 = 0.f, s4 = 0.f;
            #pragma unroll
            for (int vv = 0; vv < 3; vv++) {
                float we = Wf2e[(2 * vv) * 3 + k];
                float wo = Wf2e[(2 * vv + 1) * 3 + k];
                s1 += ap[vv] * we;  s2 += cv[vv] * we;
                s3 += ap[vv] * wo;  s4 += cv[vv] * wo;
            }
            if (tid == 0) {
                s_coef[k]     = s1;            // aA
                s_coef[3 + k] = s2 + bf2e[k];  // cA
                s_coef[6 + k] = s3;            // aB
                s_coef[9 + k] = s4;            // cB
            }
        }
        // message-combine constants: block 0 lane 0 only
        if (bid == 0 && tid == 0) {
            #pragma unroll
            for (int k = 0; k < 3; k++)
                #pragma unroll
                for (int m = 0; m < 2; m++) {
                    float u1 = 0.f, v1 = 0.f, u2 = 0.f, v2 = 0.f;
                    #pragma unroll
                    for (int e = 0; e < 4; e++) {
                        float we = Wfk[k * 16 + (2 * e) * 2 + m];
                        float wo = Wfk[k * 16 + (2 * e + 1) * 2 + m];
                        u1 += W2[e] * we;  v1 += b2[e] * we;
                        u2 += W2[e] * wo;  v2 += b2[e] * wo;
                    }
                    int km = k * 2 + m;
                    g_cc[km * 3 + 0] = v1 + v2 + bfk[km];
                    g_cc[km * 3 + 1] = u1;
                    g_cc[km * 3 + 2] = u2;
                }
            g_cc[18] = Wf2v[0]; g_cc[19] = Wf2v[1];
            g_cc[20] = Wf2v[2]; g_cc[21] = bf2v[0];
        }
    }
    __syncthreads();

    // EA/EB for my 8 rows (per-side max-subtracted; exact for softmax)
    if (tid < 8) {
        float A0 = fmaf(s_coef[0], sxi, s_coef[3]);
        float A1 = fmaf(s_coef[1], sxi, s_coef[4]);
        float A2 = fmaf(s_coef[2], sxi, s_coef[5]);
        float mA = fmaxf(A0, fmaxf(A1, A2));
        g_EA[myrow] = make_float4(__expf(A0 - mA), __expf(A1 - mA), __expf(A2 - mA), 0.f);
        float B0 = fmaf(s_coef[6], sxi, s_coef[9]);
        float B1 = fmaf(s_coef[7], sxi, s_coef[10]);
        float B2 = fmaf(s_coef[8], sxi, s_coef[11]);
        float mB = fmaxf(B0, fmaxf(B1, B2));
        g_EB[myrow] = make_float4(__expf(B0 - mB), __expf(B1 - mB), __expf(B2 - mB), 0.f);
    }

    // ================= grid-wide ticket barrier (replay-safe) ===============
    __syncthreads();
    __threadfence();                        // release phase-1 writes
    if (tid == 0) {
        unsigned long long ticket = atomicAdd(&g_bar, 1ULL);
        unsigned long long target = ticket - (ticket % GRID) + GRID;
        while (*(volatile unsigned long long*)&g_bar < target) { }
    }
    __syncthreads();
    __threadfence();                        // acquire

    // ===================== Phase 2: 2 warps per row =========================
    const int lane = tid & 31;
    const int warp = tid >> 5;              // 0..15
    const int r    = warp >> 1;             // 0..7
    const int h    = warp & 1;              // half: j in [h*512, h*512+512)
    const int i    = bid * 8 + r;           // 0..999
    const float4 ea = g_EA[i];
    const float eav[3] = {ea.x, ea.y, ea.z};

    // folded coefficients q[m][k] = c2[k,m] * ea_k
    float q0[3], q1[3];
    #pragma unroll
    for (int k = 0; k < 3; k++) {
        q0[k] = g_cc[(k * 2 + 0) * 3 + 2] * eav[k];
        q1[k] = g_cc[(k * 2 + 1) * 3 + 2] * eav[k];
    }

    float t0 = 0.f, t1 = 0.f, t2 = 0.f;
    float2 a0[4], a1[4];
    #pragma unroll
    for (int bp = 0; bp < 4; bp++) {
        a0[bp] = make_float2(0.f, 0.f);
        a1[bp] = make_float2(0.f, 0.f);
    }

    #pragma unroll 1
    for (int u = 0; u < 4; u++) {
        float4 eb[4], xa[4], xb[4];
        #pragma unroll
        for (int t = 0; t < 4; t++) {
            const int j = h * 512 + (u * 4 + t) * 32 + lane;
            eb[t] = g_EB[j];
            xa[t] = g_xt[2 * j];
            xb[t] = g_xt[2 * j + 1];
        }
        float d[4];
        #pragma unroll
        for (int t = 0; t < 4; t++)
            d[t] = fmaf(ea.x, eb[t].x, fmaf(ea.y, eb[t].y, fmaf(ea.z, eb[t].z, eb[t].w)));
        // Montgomery batch inversion: 1 MUFU per 4 pairs; d in (1,4] -> safe
        float p1 = d[0] * d[1];
        float p2 = p1 * d[2];
        float p3 = p2 * d[3];
        float rr = __fdividef(1.f, p3);
        float inv[4];
        inv[3]   = rr * p2;
        float r2 = rr * d[3];
        inv[2]   = r2 * p1;
        float r1 = r2 * d[2];
        inv[1]   = r1 * d[0];
        inv[0]   = r1 * d[1];

        #pragma unroll
        for (int t = 0; t < 4; t++) {
            float w0 = eb[t].x * inv[t];
            float w1 = eb[t].y * inv[t];
            float w2 = eb[t].z * inv[t];
            t0 += w0; t1 += w1; t2 += w2;
            float s0 = fmaf(q0[0], w0, fmaf(q0[1], w1, q0[2] * w2));
            float s1 = fmaf(q1[0], w0, fmaf(q1[1], w1, q1[2] * w2));
            float2 xp[4] = { make_float2(xa[t].x, xa[t].y), make_float2(xa[t].z, xa[t].w),
                             make_float2(xb[t].x, xb[t].y), make_float2(xb[t].z, xb[t].w) };
            float2 sp0 = make_float2(s0, s0);
            float2 sp1 = make_float2(s1, s1);
            #pragma unroll
            for (int bp = 0; bp < 4; bp++) {
                ffma2(a0[bp], sp0, xp[bp]);
                ffma2(a1[bp], sp1, xp[bp]);
            }
        }
    }

    // 19 values -> 32 slots; distributed exchange reduce within warp
    float vv[32];
    vv[0] = t0; vv[1] = t1; vv[2] = t2;
    #pragma unroll
    for (int bp = 0; bp < 4; bp++) {
        vv[3 + 2 * bp]      = a0[bp].x;  vv[3 + 2 * bp + 1]  = a0[bp].y;
        vv[11 + 2 * bp]     = a1[bp].x;  vv[11 + 2 * bp + 1] = a1[bp].y;
    }
    #pragma unroll
    for (int s = 19; s < 32; s++) vv[s] = 0.f;

    #pragma unroll
    for (int lev = 0; lev < 5; lev++) {
        const int dd = 1 << lev;
        const int half = 16 >> lev;
        const bool up = (lane & dd) != 0;
        #pragma unroll
        for (int s = 0; s < half; s++) {
            float keep = up ? vv[s + half] : vv[s];
            float send = up ? vv[s] : vv[s + half];
            float recv = __shfl_xor_sync(0xffffffffu, send, dd);
            vv[s] = keep + recv;
        }
    }
    // lane l holds total of slot bitrev5(l) -> store at canonical slot index
    const int br = ((lane & 1) << 4) | ((lane & 2) << 2) | (lane & 4)
                 | ((lane & 8) >> 2) | ((lane & 16) >> 4);
    s_v[warp][br] = vv[0];
    __syncthreads();

    // even warp of each pair finishes the row: lanes 0..7 -> 8 batch outputs
    if (h == 0 && lane < 8) {
        const int b = lane;
        const int w0i = 2 * r, w1i = 2 * r + 1;
        float xbi = ((const float*)&g_xt[2 * i])[b];
        float T0 = s_v[w0i][0] + s_v[w1i][0];
        float T1 = s_v[w0i][1] + s_v[w1i][1];
        float T2 = s_v[w0i][2] + s_v[w1i][2];
        float V0 = s_v[w0i][3 + b]  + s_v[w1i][3 + b];
        float V1 = s_v[w0i][11 + b] + s_v[w1i][11 + b];
        float eaT[3] = {eav[0] * T0, eav[1] * T1, eav[2] * T2};
        float ve0 = V0, ve1 = V1;
        #pragma unroll
        for (int k = 0; k < 3; k++) {
            ve0 += fmaf(xbi, g_cc[(k * 2 + 0) * 3 + 1], g_cc[(k * 2 + 0) * 3 + 0]) * eaT[k];
            ve1 += fmaf(xbi, g_cc[(k * 2 + 1) * 3 + 1], g_cc[(k * 2 + 1) * 3 + 0]) * eaT[k];
        }
        out[b * Nn + i] = xbi * (1.f + g_cc[20]) + g_cc[21]
                        + ve0 * g_cc[18] + ve1 * g_cc[19];
    }
}

extern "C" void kernel_launch(void* const* d_in, const int* in_sizes, int n_in,
                              void* d_out, int out_size)
{
    (void)in_sizes; (void)n_in; (void)out_size;
    k_all<<<GRID, NTHREAD>>>(
        (const float*)d_in[0],
        (const float*)d_in[1],  (const float*)d_in[2],
        (const float*)d_in[3],  (const float*)d_in[4],
        (const float*)d_in[5],  (const float*)d_in[6],
        (const float*)d_in[7],  (const float*)d_in[8],
        (const float*)d_in[9],  (const float*)d_in[10],
        (const float*)d_in[11], (const float*)d_in[12],
        (const float*)d_in[13], (const float*)d_in[14],
        (float*)d_out);
}